// round 1
// baseline (speedup 1.0000x reference)
#include <cuda_runtime.h>
#include <cuda_bf16.h>

// Problem constants
#define Bv 2
#define Nv 4096
#define Ev 512
#define Hv 8
#define Dv 64

// Scratch (device globals: allocation-free rule)
__device__ float g_qp[Bv * Hv * Nv * Dv];   // [B,H,N,D]
__device__ float g_kp[Bv * Hv * Nv * Dv];
__device__ float g_vp[Bv * Hv * Nv * Dv];
__device__ float g_attn[Bv * Nv * Ev];      // [B,N,E]

// ---------------------------------------------------------------------------
// GEMM: out[m, e] = sum_k X[m,k] * W[e,k] + bias[e]
// X: [M, 512] row-major, W: [512, 512] row-major (torch Linear weight)
// HEAD_STORE=1: scatter into [B,H,N,D] layout; else row-major [M,512].
// Tile: 64x64 output per block, BK=32, 256 threads, 4x4 microtile.
// ---------------------------------------------------------------------------
template <int HEAD_STORE>
__global__ __launch_bounds__(256)
void gemm_bias_kernel(const float* __restrict__ X,
                      const float* __restrict__ W,
                      const float* __restrict__ bias,
                      float* __restrict__ out)
{
    const int K = 512;
    __shared__ float Xs[64][32];
    __shared__ float Ws[64][33];   // +1 pad to reduce bank conflicts

    const int tid = threadIdx.x;
    const int tx = tid % 16;            // output col group
    const int ty = tid / 16;            // output row group
    const int row0 = blockIdx.y * 64;
    const int col0 = blockIdx.x * 64;

    float acc[4][4];
#pragma unroll
    for (int i = 0; i < 4; i++)
#pragma unroll
        for (int j = 0; j < 4; j++) acc[i][j] = 0.f;

    const int lr = tid / 4;             // 0..63 (load row)
    const int lc = (tid % 4) * 8;       // 0,8,16,24 (load col)

    for (int kb = 0; kb < K; kb += 32) {
        // Load X tile (vectorized, coalesced)
        {
            const float4* src = reinterpret_cast<const float4*>(
                &X[(size_t)(row0 + lr) * K + kb + lc]);
            float4 v0 = src[0], v1 = src[1];
            *reinterpret_cast<float4*>(&Xs[lr][lc])     = v0;
            *reinterpret_cast<float4*>(&Xs[lr][lc + 4]) = v1;
        }
        // Load W tile (rows = output cols); scalar STS due to pad
        {
            const float4* src = reinterpret_cast<const float4*>(
                &W[(size_t)(col0 + lr) * K + kb + lc]);
            float4 v0 = src[0], v1 = src[1];
            Ws[lr][lc + 0] = v0.x; Ws[lr][lc + 1] = v0.y;
            Ws[lr][lc + 2] = v0.z; Ws[lr][lc + 3] = v0.w;
            Ws[lr][lc + 4] = v1.x; Ws[lr][lc + 5] = v1.y;
            Ws[lr][lc + 6] = v1.z; Ws[lr][lc + 7] = v1.w;
        }
        __syncthreads();

#pragma unroll
        for (int kk = 0; kk < 32; kk++) {
            float a[4], b[4];
#pragma unroll
            for (int i = 0; i < 4; i++) a[i] = Xs[ty * 4 + i][kk];
#pragma unroll
            for (int j = 0; j < 4; j++) b[j] = Ws[tx * 4 + j][kk];
#pragma unroll
            for (int i = 0; i < 4; i++)
#pragma unroll
                for (int j = 0; j < 4; j++)
                    acc[i][j] += a[i] * b[j];
        }
        __syncthreads();
    }

#pragma unroll
    for (int i = 0; i < 4; i++) {
        const int m = row0 + ty * 4 + i;
#pragma unroll
        for (int j = 0; j < 4; j++) {
            const int e = col0 + tx * 4 + j;
            const float val = acc[i][j] + bias[e];
            if (HEAD_STORE) {
                const int b  = m / Nv;
                const int n  = m % Nv;
                const int h  = e / Dv;
                const int d  = e % Dv;
                out[(((size_t)b * Hv + h) * Nv + n) * Dv + d] = val;
            } else {
                out[(size_t)m * Ev + e] = val;
            }
        }
    }
}

// ---------------------------------------------------------------------------
// Flash attention: one thread per query row. q[64] and acc[64] in registers.
// K/V tiles (64 rows x 64) in shared memory; all K/V reads are warp-broadcast
// LDS.128 (conflict-free). Online softmax: rescale branch fires rarely.
// Grid: (N/128, B*H), block 128.
// ---------------------------------------------------------------------------
__global__ __launch_bounds__(128)
void flash_attn_kernel()
{
    __shared__ float Ksh[64][64];
    __shared__ float Vsh[64][64];

    const int bh   = blockIdx.y;                       // 0..B*H-1
    const int qrow = blockIdx.x * 128 + threadIdx.x;   // 0..N-1
    const float* Qb = g_qp + (size_t)bh * Nv * Dv;
    const float* Kb = g_kp + (size_t)bh * Nv * Dv;
    const float* Vb = g_vp + (size_t)bh * Nv * Dv;

    // Load q row, fold in 1/sqrt(D) = 0.125
    float q[64];
#pragma unroll
    for (int d4 = 0; d4 < 16; d4++) {
        float4 v = *reinterpret_cast<const float4*>(&Qb[(size_t)qrow * Dv + d4 * 4]);
        q[d4 * 4 + 0] = v.x * 0.125f;
        q[d4 * 4 + 1] = v.y * 0.125f;
        q[d4 * 4 + 2] = v.z * 0.125f;
        q[d4 * 4 + 3] = v.w * 0.125f;
    }

    float m = -3.402823466e38f;
    float l = 0.f;
    float acc[64];
#pragma unroll
    for (int d = 0; d < 64; d++) acc[d] = 0.f;

    for (int tile = 0; tile < Nv / 64; tile++) {
        __syncthreads();   // previous tile fully consumed
        const float* Ksrc = Kb + (size_t)tile * 64 * 64;
        const float* Vsrc = Vb + (size_t)tile * 64 * 64;
#pragma unroll
        for (int i = 0; i < 8; i++) {
            const int idx = threadIdx.x + i * 128;     // float4 index 0..1023
            const int r = idx / 16;
            const int c = (idx % 16) * 4;
            *reinterpret_cast<float4*>(&Ksh[r][c]) =
                *reinterpret_cast<const float4*>(&Ksrc[(size_t)idx * 4]);
            *reinterpret_cast<float4*>(&Vsh[r][c]) =
                *reinterpret_cast<const float4*>(&Vsrc[(size_t)idx * 4]);
        }
        __syncthreads();

        for (int j = 0; j < 64; j++) {
            float s0 = 0.f, s1 = 0.f, s2 = 0.f, s3 = 0.f;
#pragma unroll
            for (int d4 = 0; d4 < 16; d4++) {
                float4 kv = *reinterpret_cast<const float4*>(&Ksh[j][d4 * 4]);
                s0 += q[d4 * 4 + 0] * kv.x;
                s1 += q[d4 * 4 + 1] * kv.y;
                s2 += q[d4 * 4 + 2] * kv.z;
                s3 += q[d4 * 4 + 3] * kv.w;
            }
            const float s = (s0 + s1) + (s2 + s3);

            if (s > m) {
                const float corr = __expf(m - s);
                l *= corr;
#pragma unroll
                for (int d = 0; d < 64; d++) acc[d] *= corr;
                m = s;
            }
            const float p = __expf(s - m);
            l += p;
#pragma unroll
            for (int d4 = 0; d4 < 16; d4++) {
                float4 vv = *reinterpret_cast<const float4*>(&Vsh[j][d4 * 4]);
                acc[d4 * 4 + 0] += p * vv.x;
                acc[d4 * 4 + 1] += p * vv.y;
                acc[d4 * 4 + 2] += p * vv.z;
                acc[d4 * 4 + 3] += p * vv.w;
            }
        }
    }

    const float inv = 1.f / l;
    const int b = bh / Hv;
    const int h = bh % Hv;
    float* outp = g_attn + ((size_t)b * Nv + qrow) * Ev + h * Dv;
#pragma unroll
    for (int d4 = 0; d4 < 16; d4++) {
        float4 o;
        o.x = acc[d4 * 4 + 0] * inv;
        o.y = acc[d4 * 4 + 1] * inv;
        o.z = acc[d4 * 4 + 2] * inv;
        o.w = acc[d4 * 4 + 3] * inv;
        *reinterpret_cast<float4*>(&outp[d4 * 4]) = o;
    }
}

// ---------------------------------------------------------------------------
// kernel_launch: 3 projections -> flash attention -> output projection
// ---------------------------------------------------------------------------
extern "C" void kernel_launch(void* const* d_in, const int* in_sizes, int n_in,
                              void* d_out, int out_size)
{
    const float* q  = (const float*)d_in[0];
    const float* k  = (const float*)d_in[1];
    const float* v  = (const float*)d_in[2];
    const float* Wq = (const float*)d_in[3];
    const float* bq = (const float*)d_in[4];
    const float* Wk = (const float*)d_in[5];
    const float* bk = (const float*)d_in[6];
    const float* Wv = (const float*)d_in[7];
    const float* bv = (const float*)d_in[8];
    const float* Wo = (const float*)d_in[9];
    const float* bo = (const float*)d_in[10];
    float* out = (float*)d_out;

    float *qp, *kp, *vp, *attn;
    cudaGetSymbolAddress((void**)&qp,   g_qp);
    cudaGetSymbolAddress((void**)&kp,   g_kp);
    cudaGetSymbolAddress((void**)&vp,   g_vp);
    cudaGetSymbolAddress((void**)&attn, g_attn);

    const dim3 ggrid(Ev / 64, (Bv * Nv) / 64);   // (8, 128)
    gemm_bias_kernel<1><<<ggrid, 256>>>(q, Wq, bq, qp);
    gemm_bias_kernel<1><<<ggrid, 256>>>(k, Wk, bk, kp);
    gemm_bias_kernel<1><<<ggrid, 256>>>(v, Wv, bv, vp);

    flash_attn_kernel<<<dim3(Nv / 128, Bv * Hv), 128>>>();

    gemm_bias_kernel<0><<<ggrid, 256>>>(attn, Wo, bo, out);
}

// round 7
// speedup vs baseline: 2.3449x; 2.3449x over previous
#include <cuda_runtime.h>
#include <cuda_bf16.h>
#include <cstdint>

// Problem constants
#define Bv 2
#define Nv 4096
#define Ev 512
#define Hv 8
#define Dv 64

// Scratch (device globals: allocation-free rule)
__device__ float g_qp[Bv * Hv * Nv * Dv];   // [B,H,N,D]
__device__ float g_kp[Bv * Hv * Nv * Dv];
__device__ float g_vp[Bv * Hv * Nv * Dv];
__device__ float g_attn[Bv * Nv * Ev];      // [B,N,E]

// ---------------------------------------------------------------------------
// FFMA GEMM for projections: out[m,e] = X[m,:]·W[e,:] + b
// ---------------------------------------------------------------------------
template <int HEAD_STORE>
__global__ __launch_bounds__(256)
void gemm_bias_kernel(const float* __restrict__ X,
                      const float* __restrict__ W,
                      const float* __restrict__ bias,
                      float* __restrict__ out)
{
    const int K = 512;
    __shared__ float Xs[64][32];
    __shared__ float Ws[64][33];

    const int tid = threadIdx.x;
    const int tx = tid % 16;
    const int ty = tid / 16;
    const int row0 = blockIdx.y * 64;
    const int col0 = blockIdx.x * 64;

    float acc[4][4];
#pragma unroll
    for (int i = 0; i < 4; i++)
#pragma unroll
        for (int j = 0; j < 4; j++) acc[i][j] = 0.f;

    const int lr = tid / 4;
    const int lc = (tid % 4) * 8;

    for (int kb = 0; kb < K; kb += 32) {
        {
            const float4* src = reinterpret_cast<const float4*>(
                &X[(size_t)(row0 + lr) * K + kb + lc]);
            float4 v0 = src[0], v1 = src[1];
            *reinterpret_cast<float4*>(&Xs[lr][lc])     = v0;
            *reinterpret_cast<float4*>(&Xs[lr][lc + 4]) = v1;
        }
        {
            const float4* src = reinterpret_cast<const float4*>(
                &W[(size_t)(col0 + lr) * K + kb + lc]);
            float4 v0 = src[0], v1 = src[1];
            Ws[lr][lc + 0] = v0.x; Ws[lr][lc + 1] = v0.y;
            Ws[lr][lc + 2] = v0.z; Ws[lr][lc + 3] = v0.w;
            Ws[lr][lc + 4] = v1.x; Ws[lr][lc + 5] = v1.y;
            Ws[lr][lc + 6] = v1.z; Ws[lr][lc + 7] = v1.w;
        }
        __syncthreads();

#pragma unroll
        for (int kk = 0; kk < 32; kk++) {
            float a[4], b[4];
#pragma unroll
            for (int i = 0; i < 4; i++) a[i] = Xs[ty * 4 + i][kk];
#pragma unroll
            for (int j = 0; j < 4; j++) b[j] = Ws[tx * 4 + j][kk];
#pragma unroll
            for (int i = 0; i < 4; i++)
#pragma unroll
                for (int j = 0; j < 4; j++)
                    acc[i][j] += a[i] * b[j];
        }
        __syncthreads();
    }

#pragma unroll
    for (int i = 0; i < 4; i++) {
        const int m = row0 + ty * 4 + i;
#pragma unroll
        for (int j = 0; j < 4; j++) {
            const int e = col0 + tx * 4 + j;
            const float val = acc[i][j] + bias[e];
            if (HEAD_STORE) {
                const int b  = m / Nv;
                const int n  = m % Nv;
                const int h  = e / Dv;
                const int d  = e % Dv;
                out[(((size_t)b * Hv + h) * Nv + n) * Dv + d] = val;
            } else {
                out[(size_t)m * Ev + e] = val;
            }
        }
    }
}

// ---------------------------------------------------------------------------
// tf32 mma.sync flash attention (sm_103-safe: no tcgen05)
// Block: 128 threads, 4 warps. CTA = 128 q rows of one (b,h). KV tile = 64.
// ---------------------------------------------------------------------------

#define PAD 66      // padded row stride (floats) for all smem tiles

__device__ __forceinline__ float ex2(float x) {
    float y;
    asm("ex2.approx.ftz.f32 %0, %1;" : "=f"(y) : "f"(x));
    return y;
}

__device__ __forceinline__ uint32_t fbits(float x) { return __float_as_uint(x); }

__device__ __forceinline__ void mma_tf32(float* c,
                                         uint32_t a0, uint32_t a1, uint32_t a2, uint32_t a3,
                                         uint32_t b0, uint32_t b1) {
    asm volatile(
        "mma.sync.aligned.m16n8k8.row.col.f32.tf32.tf32.f32 "
        "{%0,%1,%2,%3}, {%4,%5,%6,%7}, {%8,%9}, {%0,%1,%2,%3};"
        : "+f"(c[0]), "+f"(c[1]), "+f"(c[2]), "+f"(c[3])
        : "r"(a0), "r"(a1), "r"(a2), "r"(a3), "r"(b0), "r"(b1));
}

__global__ __launch_bounds__(128)
void flash_attn_mma()
{
    extern __shared__ float sm[];
    float* Qs = sm;                   // [128][PAD]
    float* Ks = Qs + 128 * PAD;       // [64][PAD]
    float* Vs = Ks + 64 * PAD;        // [64][PAD]
    float* Ps = Vs + 64 * PAD;        // [128][PAD]

    const int tid  = threadIdx.x;
    const int wid  = tid >> 5;
    const int lane = tid & 31;
    const int lq   = lane >> 2;        // 0..7  (row-in-fragment group)
    const int lr4  = lane & 3;         // 0..3
    const int wq   = wid * 32;         // warp's q-row base within CTA

    const int bh = blockIdx.y;         // 0..B*H-1
    const int qt = blockIdx.x;         // 0..N/128-1

    const float* Qb = g_qp + (size_t)bh * Nv * Dv + (size_t)qt * 128 * Dv;
    const float* Kb = g_kp + (size_t)bh * Nv * Dv;
    const float* Vb = g_vp + (size_t)bh * Nv * Dv;

    // ---- load Q tile into smem, folding 0.125 * log2(e) ----
    const float QS = 0.125f * 1.4426950408889634f;
    {
        const float4* Qg = reinterpret_cast<const float4*>(Qb);
#pragma unroll
        for (int i = 0; i < 16; i++) {
            int idx = tid + i * 128;             // 0..2047 float4s
            int r = idx >> 4, c = (idx & 15) * 4;
            float4 v = Qg[idx];
            Qs[r * PAD + c + 0] = v.x * QS;
            Qs[r * PAD + c + 1] = v.y * QS;
            Qs[r * PAD + c + 2] = v.z * QS;
            Qs[r * PAD + c + 3] = v.w * QS;
        }
    }

    // per-thread row state: index [mi*2 + h], h=0 -> row lq, h=1 -> row lq+8
    float mst[4], lst[4];
#pragma unroll
    for (int i = 0; i < 4; i++) { mst[i] = -1e30f; lst[i] = 0.f; }

    float oacc[2][8][4];
#pragma unroll
    for (int mi = 0; mi < 2; mi++)
#pragma unroll
        for (int ni = 0; ni < 8; ni++)
#pragma unroll
            for (int j = 0; j < 4; j++) oacc[mi][ni][j] = 0.f;

    for (int t = 0; t < Nv / 64; t++) {
        __syncthreads();    // previous tile's K/V fully consumed

        // ---- load K/V tile (64x64 each) ----
        {
            const float4* Kg = reinterpret_cast<const float4*>(Kb + (size_t)t * 64 * Dv);
            const float4* Vg = reinterpret_cast<const float4*>(Vb + (size_t)t * 64 * Dv);
#pragma unroll
            for (int i = 0; i < 8; i++) {
                int idx = tid + i * 128;          // 0..1023 float4s
                int r = idx >> 4, c = (idx & 15) * 4;
                float4 kv = Kg[idx];
                Ks[r * PAD + c + 0] = kv.x;
                Ks[r * PAD + c + 1] = kv.y;
                Ks[r * PAD + c + 2] = kv.z;
                Ks[r * PAD + c + 3] = kv.w;
                float4 vv = Vg[idx];
                Vs[r * PAD + c + 0] = vv.x;
                Vs[r * PAD + c + 1] = vv.y;
                Vs[r * PAD + c + 2] = vv.z;
                Vs[r * PAD + c + 3] = vv.w;
            }
        }
        __syncthreads();

        // ---- S = Q · K^T   (S[32,64] per warp) ----
        float sfr[2][8][4];
#pragma unroll
        for (int mi = 0; mi < 2; mi++)
#pragma unroll
            for (int ni = 0; ni < 8; ni++)
#pragma unroll
                for (int j = 0; j < 4; j++) sfr[mi][ni][j] = 0.f;

#pragma unroll
        for (int mi = 0; mi < 2; mi++) {
            const int r0 = wq + mi * 16 + lq;
            uint32_t af[8][4];
#pragma unroll
            for (int ki = 0; ki < 8; ki++) {
                const int c0 = ki * 8 + lr4;
                af[ki][0] = fbits(Qs[r0 * PAD + c0]);
                af[ki][1] = fbits(Qs[(r0 + 8) * PAD + c0]);
                af[ki][2] = fbits(Qs[r0 * PAD + c0 + 4]);
                af[ki][3] = fbits(Qs[(r0 + 8) * PAD + c0 + 4]);
            }
#pragma unroll
            for (int ni = 0; ni < 8; ni++) {
                const int kv = ni * 8 + lq;
#pragma unroll
                for (int ki = 0; ki < 8; ki++) {
                    const int d0 = ki * 8 + lr4;
                    uint32_t b0 = fbits(Ks[kv * PAD + d0]);
                    uint32_t b1 = fbits(Ks[kv * PAD + d0 + 4]);
                    mma_tf32(sfr[mi][ni], af[ki][0], af[ki][1], af[ki][2], af[ki][3], b0, b1);
                }
            }
        }

        // ---- online softmax (log2 domain) + P store ----
#pragma unroll
        for (int mi = 0; mi < 2; mi++) {
            float pm0 = -1e30f, pm1 = -1e30f;
#pragma unroll
            for (int ni = 0; ni < 8; ni++) {
                pm0 = fmaxf(pm0, fmaxf(sfr[mi][ni][0], sfr[mi][ni][1]));
                pm1 = fmaxf(pm1, fmaxf(sfr[mi][ni][2], sfr[mi][ni][3]));
            }
            pm0 = fmaxf(pm0, __shfl_xor_sync(0xffffffffu, pm0, 1));
            pm0 = fmaxf(pm0, __shfl_xor_sync(0xffffffffu, pm0, 2));
            pm1 = fmaxf(pm1, __shfl_xor_sync(0xffffffffu, pm1, 1));
            pm1 = fmaxf(pm1, __shfl_xor_sync(0xffffffffu, pm1, 2));

            const int i0 = mi * 2, i1 = mi * 2 + 1;
            const float nm0 = fmaxf(mst[i0], pm0);
            const float nm1 = fmaxf(mst[i1], pm1);
            const float cr0 = ex2(mst[i0] - nm0);
            const float cr1 = ex2(mst[i1] - nm1);
            mst[i0] = nm0; mst[i1] = nm1;

            float s0 = 0.f, s1 = 0.f;
#pragma unroll
            for (int ni = 0; ni < 8; ni++) {
                float p0 = ex2(sfr[mi][ni][0] - nm0);
                float p1 = ex2(sfr[mi][ni][1] - nm0);
                float p2 = ex2(sfr[mi][ni][2] - nm1);
                float p3 = ex2(sfr[mi][ni][3] - nm1);
                s0 += p0 + p1;
                s1 += p2 + p3;
                sfr[mi][ni][0] = p0; sfr[mi][ni][1] = p1;
                sfr[mi][ni][2] = p2; sfr[mi][ni][3] = p3;
            }
            s0 += __shfl_xor_sync(0xffffffffu, s0, 1);
            s0 += __shfl_xor_sync(0xffffffffu, s0, 2);
            s1 += __shfl_xor_sync(0xffffffffu, s1, 1);
            s1 += __shfl_xor_sync(0xffffffffu, s1, 2);
            lst[i0] = lst[i0] * cr0 + s0;
            lst[i1] = lst[i1] * cr1 + s1;

            // rescale O accumulators
#pragma unroll
            for (int ni = 0; ni < 8; ni++) {
                oacc[mi][ni][0] *= cr0; oacc[mi][ni][1] *= cr0;
                oacc[mi][ni][2] *= cr1; oacc[mi][ni][3] *= cr1;
            }

            // store P (warp-private rows)
            const int r0 = wq + mi * 16 + lq;
#pragma unroll
            for (int ni = 0; ni < 8; ni++) {
                const int c = ni * 8 + lr4 * 2;
                *reinterpret_cast<float2*>(&Ps[r0 * PAD + c]) =
                    make_float2(sfr[mi][ni][0], sfr[mi][ni][1]);
                *reinterpret_cast<float2*>(&Ps[(r0 + 8) * PAD + c]) =
                    make_float2(sfr[mi][ni][2], sfr[mi][ni][3]);
            }
        }
        __syncwarp();

        // ---- O += P · V ----
#pragma unroll
        for (int mi = 0; mi < 2; mi++) {
            const int r0 = wq + mi * 16 + lq;
            uint32_t af[8][4];
#pragma unroll
            for (int ki = 0; ki < 8; ki++) {
                const int c0 = ki * 8 + lr4;
                af[ki][0] = fbits(Ps[r0 * PAD + c0]);
                af[ki][1] = fbits(Ps[(r0 + 8) * PAD + c0]);
                af[ki][2] = fbits(Ps[r0 * PAD + c0 + 4]);
                af[ki][3] = fbits(Ps[(r0 + 8) * PAD + c0 + 4]);
            }
#pragma unroll
            for (int ni = 0; ni < 8; ni++) {
                const int d0 = ni * 8 + lq;
#pragma unroll
                for (int ki = 0; ki < 8; ki++) {
                    const int kv0 = ki * 8 + lr4;
                    uint32_t b0 = fbits(Vs[kv0 * PAD + d0]);
                    uint32_t b1 = fbits(Vs[(kv0 + 4) * PAD + d0]);
                    mma_tf32(oacc[mi][ni], af[ki][0], af[ki][1], af[ki][2], af[ki][3], b0, b1);
                }
            }
        }
        __syncwarp();   // P reads complete before next iteration overwrites
    }

    // ---- write output rows to g_attn [B,N,E] ----
    {
        const int b = bh / Hv, h = bh % Hv;
#pragma unroll
        for (int mi = 0; mi < 2; mi++) {
#pragma unroll
            for (int hh = 0; hh < 2; hh++) {
                const int row = wq + mi * 16 + lq + hh * 8;
                const float inv = 1.f / lst[mi * 2 + hh];
                const int n = qt * 128 + row;
                float* op = g_attn + ((size_t)b * Nv + n) * Ev + h * Dv;
#pragma unroll
                for (int ni = 0; ni < 8; ni++) {
                    const int c = ni * 8 + lr4 * 2;
                    *reinterpret_cast<float2*>(&op[c]) =
                        make_float2(oacc[mi][ni][hh * 2 + 0] * inv,
                                    oacc[mi][ni][hh * 2 + 1] * inv);
                }
            }
        }
    }
}

#define FLASH_SMEM ((128 * PAD + 64 * PAD + 64 * PAD + 128 * PAD) * 4)

// ---------------------------------------------------------------------------
// kernel_launch
// ---------------------------------------------------------------------------
extern "C" void kernel_launch(void* const* d_in, const int* in_sizes, int n_in,
                              void* d_out, int out_size)
{
    const float* q  = (const float*)d_in[0];
    const float* k  = (const float*)d_in[1];
    const float* v  = (const float*)d_in[2];
    const float* Wq = (const float*)d_in[3];
    const float* bq = (const float*)d_in[4];
    const float* Wk = (const float*)d_in[5];
    const float* bk = (const float*)d_in[6];
    const float* Wv = (const float*)d_in[7];
    const float* bv = (const float*)d_in[8];
    const float* Wo = (const float*)d_in[9];
    const float* bo = (const float*)d_in[10];
    float* out = (float*)d_out;

    float *qp, *kp, *vp, *attn;
    cudaGetSymbolAddress((void**)&qp,   g_qp);
    cudaGetSymbolAddress((void**)&kp,   g_kp);
    cudaGetSymbolAddress((void**)&vp,   g_vp);
    cudaGetSymbolAddress((void**)&attn, g_attn);

    cudaFuncSetAttribute(flash_attn_mma,
                         cudaFuncAttributeMaxDynamicSharedMemorySize, FLASH_SMEM);

    const dim3 ggrid(Ev / 64, (Bv * Nv) / 64);
    gemm_bias_kernel<1><<<ggrid, 256>>>(q, Wq, bq, qp);
    gemm_bias_kernel<1><<<ggrid, 256>>>(k, Wk, bk, kp);
    gemm_bias_kernel<1><<<ggrid, 256>>>(v, Wv, bv, vp);

    flash_attn_mma<<<dim3(Nv / 128, Bv * Hv), 128, FLASH_SMEM>>>();

    gemm_bias_kernel<0><<<ggrid, 256>>>(attn, Wo, bo, out);
}

// round 16
// speedup vs baseline: 3.8068x; 1.6234x over previous
#include <cuda_runtime.h>
#include <cuda_bf16.h>
#include <cstdint>

// Problem constants
#define Bv 2
#define Nv 4096
#define Ev 512
#define Hv 8
#define Dv 64

// Scratch (device globals: allocation-free rule)
__device__ float g_qp[Bv * Hv * Nv * Dv];   // [B,H,N,D]
__device__ float g_kp[Bv * Hv * Nv * Dv];
__device__ float g_vp[Bv * Hv * Nv * Dv];
__device__ float g_attn[Bv * Nv * Ev];      // [B,N,E]

__device__ __forceinline__ float ex2(float x) {
    float y;
    asm("ex2.approx.ftz.f32 %0, %1;" : "=f"(y) : "f"(x));
    return y;
}
__device__ __forceinline__ uint32_t fbits(float x) { return __float_as_uint(x); }

__device__ __forceinline__ void mma_tf32(float* c,
                                         uint32_t a0, uint32_t a1, uint32_t a2, uint32_t a3,
                                         uint32_t b0, uint32_t b1) {
    asm volatile(
        "mma.sync.aligned.m16n8k8.row.col.f32.tf32.tf32.f32 "
        "{%0,%1,%2,%3}, {%4,%5,%6,%7}, {%8,%9}, {%0,%1,%2,%3};"
        : "+f"(c[0]), "+f"(c[1]), "+f"(c[2]), "+f"(c[3])
        : "r"(a0), "r"(a1), "r"(a2), "r"(a3), "r"(b0), "r"(b1));
}

// ---------------------------------------------------------------------------
// tf32 mma.sync GEMM core: out[m,e] = X[m,:]·W[e,:] + b
// CTA tile 128x64, 8 warps, warp = 16 rows x 64 cols. BK = 32.
// ---------------------------------------------------------------------------
#define BKP 36   // 32 + 4 pad (stride mod 32 = 4: conflict-free frag loads)

template <int HEAD_STORE>
__device__ __forceinline__
void gemm_mma_body(const float* __restrict__ X,
                   const float* __restrict__ W,
                   const float* __restrict__ bias,
                   float* __restrict__ out)
{
    __shared__ float Xs[128 * BKP];
    __shared__ float Ws[64 * BKP];

    const int tid  = threadIdx.x;
    const int wid  = tid >> 5;
    const int lane = tid & 31;
    const int lq   = lane >> 2;
    const int lr4  = lane & 3;
    const int wr   = wid * 16;

    const int row0 = blockIdx.y * 128;
    const int col0 = blockIdx.x * 64;

    float oacc[8][4];
#pragma unroll
    for (int ni = 0; ni < 8; ni++)
#pragma unroll
        for (int j = 0; j < 4; j++) oacc[ni][j] = 0.f;

    for (int kb = 0; kb < 512; kb += 32) {
        __syncthreads();
        // X tile 128x32 = 1024 float4, 256 threads x 4
#pragma unroll
        for (int i = 0; i < 4; i++) {
            int idx = tid + i * 256;
            int r = idx >> 3, c = (idx & 7) * 4;
            float4 v = *reinterpret_cast<const float4*>(
                &X[(size_t)(row0 + r) * 512 + kb + c]);
            Xs[r * BKP + c + 0] = v.x; Xs[r * BKP + c + 1] = v.y;
            Xs[r * BKP + c + 2] = v.z; Xs[r * BKP + c + 3] = v.w;
        }
        // W tile 64x32 = 512 float4, 256 threads x 2
#pragma unroll
        for (int i = 0; i < 2; i++) {
            int idx = tid + i * 256;
            int r = idx >> 3, c = (idx & 7) * 4;
            float4 v = *reinterpret_cast<const float4*>(
                &W[(size_t)(col0 + r) * 512 + kb + c]);
            Ws[r * BKP + c + 0] = v.x; Ws[r * BKP + c + 1] = v.y;
            Ws[r * BKP + c + 2] = v.z; Ws[r * BKP + c + 3] = v.w;
        }
        __syncthreads();

        uint32_t af[4][4];
#pragma unroll
        for (int ki = 0; ki < 4; ki++) {
            const int c0 = ki * 8 + lr4;
            af[ki][0] = fbits(Xs[(wr + lq) * BKP + c0]);
            af[ki][1] = fbits(Xs[(wr + lq + 8) * BKP + c0]);
            af[ki][2] = fbits(Xs[(wr + lq) * BKP + c0 + 4]);
            af[ki][3] = fbits(Xs[(wr + lq + 8) * BKP + c0 + 4]);
        }
#pragma unroll
        for (int ni = 0; ni < 8; ni++) {
            const int e = ni * 8 + lq;
#pragma unroll
            for (int ki = 0; ki < 4; ki++) {
                const int c0 = ki * 8 + lr4;
                uint32_t b0 = fbits(Ws[e * BKP + c0]);
                uint32_t b1 = fbits(Ws[e * BKP + c0 + 4]);
                mma_tf32(oacc[ni], af[ki][0], af[ki][1], af[ki][2], af[ki][3], b0, b1);
            }
        }
    }

    // epilogue: bias + store
#pragma unroll
    for (int ni = 0; ni < 8; ni++) {
        const int e = col0 + ni * 8 + lr4 * 2;
        const float b0 = bias[e], b1 = bias[e + 1];
#pragma unroll
        for (int hh = 0; hh < 2; hh++) {
            const int m = row0 + wr + lq + hh * 8;
            float2 v = make_float2(oacc[ni][hh * 2 + 0] + b0,
                                   oacc[ni][hh * 2 + 1] + b1);
            if (HEAD_STORE) {
                const int bb = m / Nv, n = m % Nv;
                const int h = e / Dv, d = e % Dv;
                *reinterpret_cast<float2*>(
                    &out[(((size_t)bb * Hv + h) * Nv + n) * Dv + d]) = v;
            } else {
                *reinterpret_cast<float2*>(&out[(size_t)m * Ev + e]) = v;
            }
        }
    }
}

// Q/K/V projections fused into one launch via blockIdx.z (identical math).
__global__ __launch_bounds__(256)
void gemm_mma_qkv(const float* __restrict__ q, const float* __restrict__ k,
                  const float* __restrict__ v,
                  const float* __restrict__ Wq, const float* __restrict__ Wk,
                  const float* __restrict__ Wv,
                  const float* __restrict__ bq, const float* __restrict__ bk,
                  const float* __restrict__ bv,
                  float* __restrict__ qp, float* __restrict__ kp,
                  float* __restrict__ vp)
{
    const int z = blockIdx.z;
    const float* X    = (z == 0) ? q  : (z == 1) ? k  : v;
    const float* W    = (z == 0) ? Wq : (z == 1) ? Wk : Wv;
    const float* bias = (z == 0) ? bq : (z == 1) ? bk : bv;
    float*       out  = (z == 0) ? qp : (z == 1) ? kp : vp;
    gemm_mma_body<1>(X, W, bias, out);
}

__global__ __launch_bounds__(256)
void gemm_mma_o(const float* __restrict__ X, const float* __restrict__ W,
                const float* __restrict__ bias, float* __restrict__ out)
{
    gemm_mma_body<0>(X, W, bias, out);
}

// ---------------------------------------------------------------------------
// tf32 mma.sync flash attention.
// 256 threads / 8 warps; warp = 16 q-rows. KV tile 64. Q frags in registers.
// ---------------------------------------------------------------------------
#define PAD 68      // stride mod 32 = 4 -> conflict-free fragment LDS

__global__ __launch_bounds__(256, 2)
void flash_attn_mma()
{
    extern __shared__ float sm[];
    float* Ks = sm;                   // [64][PAD]
    float* Vs = Ks + 64 * PAD;        // [64][PAD]
    float* Ps = Vs + 64 * PAD;        // [128][PAD]

    const int tid  = threadIdx.x;
    const int wid  = tid >> 5;         // 0..7
    const int lane = tid & 31;
    const int lq   = lane >> 2;
    const int lr4  = lane & 3;
    const int wq   = wid * 16;         // warp's q-row base

    const int bh = blockIdx.y;
    const int qt = blockIdx.x;

    const float* Qb = g_qp + (size_t)bh * Nv * Dv + (size_t)qt * 128 * Dv;
    const float* Kb = g_kp + (size_t)bh * Nv * Dv;
    const float* Vb = g_vp + (size_t)bh * Nv * Dv;

    // ---- Q fragments in registers (folding 0.125*log2(e)) ----
    const float QS = 0.125f * 1.4426950408889634f;
    uint32_t aq[8][4];
#pragma unroll
    for (int ki = 0; ki < 8; ki++) {
        const int c0 = ki * 8 + lr4;
        aq[ki][0] = fbits(Qb[(size_t)(wq + lq) * Dv + c0] * QS);
        aq[ki][1] = fbits(Qb[(size_t)(wq + lq + 8) * Dv + c0] * QS);
        aq[ki][2] = fbits(Qb[(size_t)(wq + lq) * Dv + c0 + 4] * QS);
        aq[ki][3] = fbits(Qb[(size_t)(wq + lq + 8) * Dv + c0 + 4] * QS);
    }

    float mst[2] = {-1e30f, -1e30f}, lst[2] = {0.f, 0.f};
    float oacc[8][4];
#pragma unroll
    for (int ni = 0; ni < 8; ni++)
#pragma unroll
        for (int j = 0; j < 4; j++) oacc[ni][j] = 0.f;

    for (int t = 0; t < Nv / 64; t++) {
        __syncthreads();    // previous tile's K/V/P fully consumed

        // ---- load K/V tile (64x64 each): 1024 float4 over 256 threads ----
        {
            const float4* Kg = reinterpret_cast<const float4*>(Kb + (size_t)t * 64 * Dv);
            const float4* Vg = reinterpret_cast<const float4*>(Vb + (size_t)t * 64 * Dv);
#pragma unroll
            for (int i = 0; i < 4; i++) {
                int idx = tid + i * 256;
                int r = idx >> 4, c = (idx & 15) * 4;
                float4 kv = Kg[idx];
                Ks[r * PAD + c + 0] = kv.x; Ks[r * PAD + c + 1] = kv.y;
                Ks[r * PAD + c + 2] = kv.z; Ks[r * PAD + c + 3] = kv.w;
                float4 vv = Vg[idx];
                Vs[r * PAD + c + 0] = vv.x; Vs[r * PAD + c + 1] = vv.y;
                Vs[r * PAD + c + 2] = vv.z; Vs[r * PAD + c + 3] = vv.w;
            }
        }
        __syncthreads();

        // ---- S = Q · K^T  (16x64 per warp) ----
        float sfr[8][4];
#pragma unroll
        for (int ni = 0; ni < 8; ni++)
#pragma unroll
            for (int j = 0; j < 4; j++) sfr[ni][j] = 0.f;

#pragma unroll
        for (int ni = 0; ni < 8; ni++) {
            const int kv = ni * 8 + lq;
#pragma unroll
            for (int ki = 0; ki < 8; ki++) {
                const int d0 = ki * 8 + lr4;
                uint32_t b0 = fbits(Ks[kv * PAD + d0]);
                uint32_t b1 = fbits(Ks[kv * PAD + d0 + 4]);
                mma_tf32(sfr[ni], aq[ki][0], aq[ki][1], aq[ki][2], aq[ki][3], b0, b1);
            }
        }

        // ---- online softmax (log2 domain) ----
        float pm0 = -1e30f, pm1 = -1e30f;
#pragma unroll
        for (int ni = 0; ni < 8; ni++) {
            pm0 = fmaxf(pm0, fmaxf(sfr[ni][0], sfr[ni][1]));
            pm1 = fmaxf(pm1, fmaxf(sfr[ni][2], sfr[ni][3]));
        }
        pm0 = fmaxf(pm0, __shfl_xor_sync(0xffffffffu, pm0, 1));
        pm0 = fmaxf(pm0, __shfl_xor_sync(0xffffffffu, pm0, 2));
        pm1 = fmaxf(pm1, __shfl_xor_sync(0xffffffffu, pm1, 1));
        pm1 = fmaxf(pm1, __shfl_xor_sync(0xffffffffu, pm1, 2));

        const float nm0 = fmaxf(mst[0], pm0);
        const float nm1 = fmaxf(mst[1], pm1);
        const float cr0 = ex2(mst[0] - nm0);
        const float cr1 = ex2(mst[1] - nm1);
        mst[0] = nm0; mst[1] = nm1;

        float s0 = 0.f, s1 = 0.f;
#pragma unroll
        for (int ni = 0; ni < 8; ni++) {
            float p0 = ex2(sfr[ni][0] - nm0);
            float p1 = ex2(sfr[ni][1] - nm0);
            float p2 = ex2(sfr[ni][2] - nm1);
            float p3 = ex2(sfr[ni][3] - nm1);
            s0 += p0 + p1; s1 += p2 + p3;
            sfr[ni][0] = p0; sfr[ni][1] = p1;
            sfr[ni][2] = p2; sfr[ni][3] = p3;
        }
        s0 += __shfl_xor_sync(0xffffffffu, s0, 1);
        s0 += __shfl_xor_sync(0xffffffffu, s0, 2);
        s1 += __shfl_xor_sync(0xffffffffu, s1, 1);
        s1 += __shfl_xor_sync(0xffffffffu, s1, 2);
        lst[0] = lst[0] * cr0 + s0;
        lst[1] = lst[1] * cr1 + s1;

#pragma unroll
        for (int ni = 0; ni < 8; ni++) {
            oacc[ni][0] *= cr0; oacc[ni][1] *= cr0;
            oacc[ni][2] *= cr1; oacc[ni][3] *= cr1;
        }

        // ---- store P (warp-private rows) ----
#pragma unroll
        for (int ni = 0; ni < 8; ni++) {
            const int c = ni * 8 + lr4 * 2;
            *reinterpret_cast<float2*>(&Ps[(wq + lq) * PAD + c]) =
                make_float2(sfr[ni][0], sfr[ni][1]);
            *reinterpret_cast<float2*>(&Ps[(wq + lq + 8) * PAD + c]) =
                make_float2(sfr[ni][2], sfr[ni][3]);
        }
        __syncwarp();

        // ---- O += P · V ----
        uint32_t ap[8][4];
#pragma unroll
        for (int ki = 0; ki < 8; ki++) {
            const int c0 = ki * 8 + lr4;
            ap[ki][0] = fbits(Ps[(wq + lq) * PAD + c0]);
            ap[ki][1] = fbits(Ps[(wq + lq + 8) * PAD + c0]);
            ap[ki][2] = fbits(Ps[(wq + lq) * PAD + c0 + 4]);
            ap[ki][3] = fbits(Ps[(wq + lq + 8) * PAD + c0 + 4]);
        }
#pragma unroll
        for (int ni = 0; ni < 8; ni++) {
            const int d0 = ni * 8 + lq;
#pragma unroll
            for (int ki = 0; ki < 8; ki++) {
                const int kv0 = ki * 8 + lr4;
                uint32_t b0 = fbits(Vs[kv0 * PAD + d0]);
                uint32_t b1 = fbits(Vs[(kv0 + 4) * PAD + d0]);
                mma_tf32(oacc[ni], ap[ki][0], ap[ki][1], ap[ki][2], ap[ki][3], b0, b1);
            }
        }
        __syncwarp();
    }

    // ---- write output rows to g_attn [B,N,E] ----
    {
        const int b = bh / Hv, h = bh % Hv;
#pragma unroll
        for (int hh = 0; hh < 2; hh++) {
            const int row = wq + lq + hh * 8;
            const float inv = 1.f / lst[hh];
            const int n = qt * 128 + row;
            float* op = g_attn + ((size_t)b * Nv + n) * Ev + h * Dv;
#pragma unroll
            for (int ni = 0; ni < 8; ni++) {
                const int c = ni * 8 + lr4 * 2;
                *reinterpret_cast<float2*>(&op[c]) =
                    make_float2(oacc[ni][hh * 2 + 0] * inv,
                                oacc[ni][hh * 2 + 1] * inv);
            }
        }
    }
}

#define FLASH_SMEM ((64 + 64 + 128) * PAD * 4)   // 69632 bytes

// ---------------------------------------------------------------------------
// kernel_launch
// ---------------------------------------------------------------------------
extern "C" void kernel_launch(void* const* d_in, const int* in_sizes, int n_in,
                              void* d_out, int out_size)
{
    const float* q  = (const float*)d_in[0];
    const float* k  = (const float*)d_in[1];
    const float* v  = (const float*)d_in[2];
    const float* Wq = (const float*)d_in[3];
    const float* bq = (const float*)d_in[4];
    const float* Wk = (const float*)d_in[5];
    const float* bk = (const float*)d_in[6];
    const float* Wv = (const float*)d_in[7];
    const float* bv = (const float*)d_in[8];
    const float* Wo = (const float*)d_in[9];
    const float* bo = (const float*)d_in[10];
    float* out = (float*)d_out;

    float *qp, *kp, *vp, *attn;
    cudaGetSymbolAddress((void**)&qp,   g_qp);
    cudaGetSymbolAddress((void**)&kp,   g_kp);
    cudaGetSymbolAddress((void**)&vp,   g_vp);
    cudaGetSymbolAddress((void**)&attn, g_attn);

    cudaFuncSetAttribute(flash_attn_mma,
                         cudaFuncAttributeMaxDynamicSharedMemorySize, FLASH_SMEM);

    const dim3 qkvgrid(Ev / 64, (Bv * Nv) / 128, 3);   // (8, 64, 3)
    gemm_mma_qkv<<<qkvgrid, 256>>>(q, k, v, Wq, Wk, Wv, bq, bk, bv, qp, kp, vp);

    flash_attn_mma<<<dim3(Nv / 128, Bv * Hv), 256, FLASH_SMEM>>>();

    const dim3 ogrid(Ev / 64, (Bv * Nv) / 128);        // (8, 64)
    gemm_mma_o<<<ogrid, 256>>>(attn, Wo, bo, out);
}

// round 17
// speedup vs baseline: 4.1945x; 1.1018x over previous
#include <cuda_runtime.h>
#include <cuda_bf16.h>
#include <cstdint>

// Problem constants
#define Bv 2
#define Nv 4096
#define Ev 512
#define Hv 8
#define Dv 64

// Scratch (device globals: allocation-free rule)
__device__ float g_qp[Bv * Hv * Nv * Dv];   // [B,H,N,D]
__device__ float g_kp[Bv * Hv * Nv * Dv];
__device__ float g_vp[Bv * Hv * Nv * Dv];
__device__ float g_attn[Bv * Nv * Ev];      // [B,N,E]

__device__ __forceinline__ float ex2(float x) {
    float y;
    asm("ex2.approx.ftz.f32 %0, %1;" : "=f"(y) : "f"(x));
    return y;
}
__device__ __forceinline__ uint32_t fbits(float x) { return __float_as_uint(x); }

__device__ __forceinline__ void mma_tf32(float* c,
                                         uint32_t a0, uint32_t a1, uint32_t a2, uint32_t a3,
                                         uint32_t b0, uint32_t b1) {
    asm volatile(
        "mma.sync.aligned.m16n8k8.row.col.f32.tf32.tf32.f32 "
        "{%0,%1,%2,%3}, {%4,%5,%6,%7}, {%8,%9}, {%0,%1,%2,%3};"
        : "+f"(c[0]), "+f"(c[1]), "+f"(c[2]), "+f"(c[3])
        : "r"(a0), "r"(a1), "r"(a2), "r"(a3), "r"(b0), "r"(b1));
}

// cp.async helpers (16B, L1-bypass)
__device__ __forceinline__ void cpa16(uint32_t dst, const void* src) {
    asm volatile("cp.async.cg.shared.global [%0], [%1], 16;"
                 :: "r"(dst), "l"(src) : "memory");
}
__device__ __forceinline__ void cpa_commit() {
    asm volatile("cp.async.commit_group;" ::: "memory");
}
__device__ __forceinline__ void cpa_wait0() {
    asm volatile("cp.async.wait_group 0;" ::: "memory");
}
__device__ __forceinline__ uint32_t s2u(const void* p) {
    return (uint32_t)__cvta_generic_to_shared(p);
}

// ---------------------------------------------------------------------------
// tf32 mma.sync GEMM core, cp.async double-buffered.
// CTA tile 128x64, 8 warps, warp = 16 rows x 64 cols. BK = 32.
// ---------------------------------------------------------------------------
#define BKP 36   // 32 + 4 pad (stride mod 32 = 4: conflict-free frag loads)
#define XBUF (128 * BKP)
#define WBUF (64 * BKP)
#define GEMM_SMEM ((2 * XBUF + 2 * WBUF) * 4)   // 55296 bytes

template <int HEAD_STORE>
__device__ __forceinline__
void gemm_mma_body(const float* __restrict__ X,
                   const float* __restrict__ W,
                   const float* __restrict__ bias,
                   float* __restrict__ out)
{
    extern __shared__ float gsm[];
    float* Xb = gsm;                 // [2][128*BKP]
    float* Wb = gsm + 2 * XBUF;      // [2][64*BKP]

    const int tid  = threadIdx.x;
    const int wid  = tid >> 5;
    const int lane = tid & 31;
    const int lq   = lane >> 2;
    const int lr4  = lane & 3;
    const int wr   = wid * 16;

    const int row0 = blockIdx.y * 128;
    const int col0 = blockIdx.x * 64;

    // per-thread load coords (same for every kb)
    const int xr = tid >> 3, xc = (tid & 7) * 4;   // +2 more rows at +32, +64, +96 via i

    float oacc[8][4];
#pragma unroll
    for (int ni = 0; ni < 8; ni++)
#pragma unroll
        for (int j = 0; j < 4; j++) oacc[ni][j] = 0.f;

    // ---- prefetch kb=0 into buffer 0 ----
    {
#pragma unroll
        for (int i = 0; i < 4; i++) {
            int idx = tid + i * 256;
            int r = idx >> 3, c = (idx & 7) * 4;
            cpa16(s2u(&Xb[r * BKP + c]), &X[(size_t)(row0 + r) * 512 + c]);
        }
#pragma unroll
        for (int i = 0; i < 2; i++) {
            int idx = tid + i * 256;
            int r = idx >> 3, c = (idx & 7) * 4;
            cpa16(s2u(&Wb[r * BKP + c]), &W[(size_t)(col0 + r) * 512 + c]);
        }
        cpa_commit();
    }

    for (int kbi = 0; kbi < 16; kbi++) {
        const int cur = kbi & 1;
        cpa_wait0();
        __syncthreads();   // tile kbi ready; prior iter's reads of other buffer done

        if (kbi + 1 < 16) {
            const int nxt = cur ^ 1;
            const int kb2 = (kbi + 1) * 32;
            float* Xn = Xb + nxt * XBUF;
            float* Wn = Wb + nxt * WBUF;
#pragma unroll
            for (int i = 0; i < 4; i++) {
                int idx = tid + i * 256;
                int r = idx >> 3, c = (idx & 7) * 4;
                cpa16(s2u(&Xn[r * BKP + c]), &X[(size_t)(row0 + r) * 512 + kb2 + c]);
            }
#pragma unroll
            for (int i = 0; i < 2; i++) {
                int idx = tid + i * 256;
                int r = idx >> 3, c = (idx & 7) * 4;
                cpa16(s2u(&Wn[r * BKP + c]), &W[(size_t)(col0 + r) * 512 + kb2 + c]);
            }
            cpa_commit();
        }

        const float* Xs = Xb + cur * XBUF;
        const float* Ws = Wb + cur * WBUF;

        uint32_t af[4][4];
#pragma unroll
        for (int ki = 0; ki < 4; ki++) {
            const int c0 = ki * 8 + lr4;
            af[ki][0] = fbits(Xs[(wr + lq) * BKP + c0]);
            af[ki][1] = fbits(Xs[(wr + lq + 8) * BKP + c0]);
            af[ki][2] = fbits(Xs[(wr + lq) * BKP + c0 + 4]);
            af[ki][3] = fbits(Xs[(wr + lq + 8) * BKP + c0 + 4]);
        }
#pragma unroll
        for (int ni = 0; ni < 8; ni++) {
            const int e = ni * 8 + lq;
#pragma unroll
            for (int ki = 0; ki < 4; ki++) {
                const int c0 = ki * 8 + lr4;
                uint32_t b0 = fbits(Ws[e * BKP + c0]);
                uint32_t b1 = fbits(Ws[e * BKP + c0 + 4]);
                mma_tf32(oacc[ni], af[ki][0], af[ki][1], af[ki][2], af[ki][3], b0, b1);
            }
        }
    }

    // epilogue: bias + store
#pragma unroll
    for (int ni = 0; ni < 8; ni++) {
        const int e = col0 + ni * 8 + lr4 * 2;
        const float b0 = bias[e], b1 = bias[e + 1];
#pragma unroll
        for (int hh = 0; hh < 2; hh++) {
            const int m = row0 + wr + lq + hh * 8;
            float2 v = make_float2(oacc[ni][hh * 2 + 0] + b0,
                                   oacc[ni][hh * 2 + 1] + b1);
            if (HEAD_STORE) {
                const int bb = m / Nv, n = m % Nv;
                const int h = e / Dv, d = e % Dv;
                *reinterpret_cast<float2*>(
                    &out[(((size_t)bb * Hv + h) * Nv + n) * Dv + d]) = v;
            } else {
                *reinterpret_cast<float2*>(&out[(size_t)m * Ev + e]) = v;
            }
        }
    }
}

// Q/K/V projections fused into one launch via blockIdx.z (identical math).
__global__ __launch_bounds__(256)
void gemm_mma_qkv(const float* __restrict__ q, const float* __restrict__ k,
                  const float* __restrict__ v,
                  const float* __restrict__ Wq, const float* __restrict__ Wk,
                  const float* __restrict__ Wv,
                  const float* __restrict__ bq, const float* __restrict__ bk,
                  const float* __restrict__ bv,
                  float* __restrict__ qp, float* __restrict__ kp,
                  float* __restrict__ vp)
{
    const int z = blockIdx.z;
    const float* X    = (z == 0) ? q  : (z == 1) ? k  : v;
    const float* W    = (z == 0) ? Wq : (z == 1) ? Wk : Wv;
    const float* bias = (z == 0) ? bq : (z == 1) ? bk : bv;
    float*       out  = (z == 0) ? qp : (z == 1) ? kp : vp;
    gemm_mma_body<1>(X, W, bias, out);
}

__global__ __launch_bounds__(256)
void gemm_mma_o(const float* __restrict__ X, const float* __restrict__ W,
                const float* __restrict__ bias, float* __restrict__ out)
{
    gemm_mma_body<0>(X, W, bias, out);
}

// ---------------------------------------------------------------------------
// tf32 mma.sync flash attention, cp.async double-buffered K/V.
// 256 threads / 8 warps; warp = 16 q-rows. KV tile 64. Q frags in registers.
// ---------------------------------------------------------------------------
#define PAD 68              // stride mod 32 = 4 -> conflict-free fragment LDS
#define KVS (64 * PAD)      // one K or V buffer, in floats
#define FLASH_SMEM ((4 * KVS + 128 * PAD) * 4)   // 104448 bytes

__global__ __launch_bounds__(256, 2)
void flash_attn_mma()
{
    extern __shared__ float sm[];
    float* Kb2 = sm;                    // [2][KVS]
    float* Vb2 = sm + 2 * KVS;          // [2][KVS]
    float* Ps  = sm + 4 * KVS;          // [128][PAD]

    const int tid  = threadIdx.x;
    const int wid  = tid >> 5;         // 0..7
    const int lane = tid & 31;
    const int lq   = lane >> 2;
    const int lr4  = lane & 3;
    const int wq   = wid * 16;         // warp's q-row base

    const int bh = blockIdx.y;
    const int qt = blockIdx.x;

    const float* Qb = g_qp + (size_t)bh * Nv * Dv + (size_t)qt * 128 * Dv;
    const float* Kg = g_kp + (size_t)bh * Nv * Dv;
    const float* Vg = g_vp + (size_t)bh * Nv * Dv;

    // ---- prefetch KV tile 0 into buffer 0 ----
    {
#pragma unroll
        for (int i = 0; i < 4; i++) {
            int idx = tid + i * 256;
            int r = idx >> 4, c = (idx & 15) * 4;
            cpa16(s2u(&Kb2[r * PAD + c]), &Kg[(size_t)idx * 4]);
            cpa16(s2u(&Vb2[r * PAD + c]), &Vg[(size_t)idx * 4]);
        }
        cpa_commit();
    }

    // ---- Q fragments in registers (folding 0.125*log2(e)), overlapped with prefetch ----
    const float QS = 0.125f * 1.4426950408889634f;
    uint32_t aq[8][4];
#pragma unroll
    for (int ki = 0; ki < 8; ki++) {
        const int c0 = ki * 8 + lr4;
        aq[ki][0] = fbits(Qb[(size_t)(wq + lq) * Dv + c0] * QS);
        aq[ki][1] = fbits(Qb[(size_t)(wq + lq + 8) * Dv + c0] * QS);
        aq[ki][2] = fbits(Qb[(size_t)(wq + lq) * Dv + c0 + 4] * QS);
        aq[ki][3] = fbits(Qb[(size_t)(wq + lq + 8) * Dv + c0 + 4] * QS);
    }

    float mst[2] = {-1e30f, -1e30f}, lst[2] = {0.f, 0.f};
    float oacc[8][4];
#pragma unroll
    for (int ni = 0; ni < 8; ni++)
#pragma unroll
        for (int j = 0; j < 4; j++) oacc[ni][j] = 0.f;

    for (int t = 0; t < Nv / 64; t++) {
        const int cur = t & 1;
        cpa_wait0();
        __syncthreads();   // tile t ready; all warps done reading other buffer

        // ---- prefetch tile t+1 into other buffer ----
        if (t + 1 < Nv / 64) {
            const int nxt = cur ^ 1;
            const float* Kn = Kg + (size_t)(t + 1) * 64 * Dv;
            const float* Vn = Vg + (size_t)(t + 1) * 64 * Dv;
            float* Kd = Kb2 + nxt * KVS;
            float* Vd = Vb2 + nxt * KVS;
#pragma unroll
            for (int i = 0; i < 4; i++) {
                int idx = tid + i * 256;
                int r = idx >> 4, c = (idx & 15) * 4;
                cpa16(s2u(&Kd[r * PAD + c]), &Kn[(size_t)idx * 4]);
                cpa16(s2u(&Vd[r * PAD + c]), &Vn[(size_t)idx * 4]);
            }
            cpa_commit();
        }

        const float* Ks = Kb2 + cur * KVS;
        const float* Vs = Vb2 + cur * KVS;

        // ---- S = Q · K^T  (16x64 per warp) ----
        float sfr[8][4];
#pragma unroll
        for (int ni = 0; ni < 8; ni++)
#pragma unroll
            for (int j = 0; j < 4; j++) sfr[ni][j] = 0.f;

#pragma unroll
        for (int ni = 0; ni < 8; ni++) {
            const int kv = ni * 8 + lq;
#pragma unroll
            for (int ki = 0; ki < 8; ki++) {
                const int d0 = ki * 8 + lr4;
                uint32_t b0 = fbits(Ks[kv * PAD + d0]);
                uint32_t b1 = fbits(Ks[kv * PAD + d0 + 4]);
                mma_tf32(sfr[ni], aq[ki][0], aq[ki][1], aq[ki][2], aq[ki][3], b0, b1);
            }
        }

        // ---- online softmax (log2 domain) ----
        float pm0 = -1e30f, pm1 = -1e30f;
#pragma unroll
        for (int ni = 0; ni < 8; ni++) {
            pm0 = fmaxf(pm0, fmaxf(sfr[ni][0], sfr[ni][1]));
            pm1 = fmaxf(pm1, fmaxf(sfr[ni][2], sfr[ni][3]));
        }
        pm0 = fmaxf(pm0, __shfl_xor_sync(0xffffffffu, pm0, 1));
        pm0 = fmaxf(pm0, __shfl_xor_sync(0xffffffffu, pm0, 2));
        pm1 = fmaxf(pm1, __shfl_xor_sync(0xffffffffu, pm1, 1));
        pm1 = fmaxf(pm1, __shfl_xor_sync(0xffffffffu, pm1, 2));

        const float nm0 = fmaxf(mst[0], pm0);
        const float nm1 = fmaxf(mst[1], pm1);
        const float cr0 = ex2(mst[0] - nm0);
        const float cr1 = ex2(mst[1] - nm1);
        mst[0] = nm0; mst[1] = nm1;

        float s0 = 0.f, s1 = 0.f;
#pragma unroll
        for (int ni = 0; ni < 8; ni++) {
            float p0 = ex2(sfr[ni][0] - nm0);
            float p1 = ex2(sfr[ni][1] - nm0);
            float p2 = ex2(sfr[ni][2] - nm1);
            float p3 = ex2(sfr[ni][3] - nm1);
            s0 += p0 + p1; s1 += p2 + p3;
            sfr[ni][0] = p0; sfr[ni][1] = p1;
            sfr[ni][2] = p2; sfr[ni][3] = p3;
        }
        s0 += __shfl_xor_sync(0xffffffffu, s0, 1);
        s0 += __shfl_xor_sync(0xffffffffu, s0, 2);
        s1 += __shfl_xor_sync(0xffffffffu, s1, 1);
        s1 += __shfl_xor_sync(0xffffffffu, s1, 2);
        lst[0] = lst[0] * cr0 + s0;
        lst[1] = lst[1] * cr1 + s1;

#pragma unroll
        for (int ni = 0; ni < 8; ni++) {
            oacc[ni][0] *= cr0; oacc[ni][1] *= cr0;
            oacc[ni][2] *= cr1; oacc[ni][3] *= cr1;
        }

        // ---- store P (warp-private rows) ----
#pragma unroll
        for (int ni = 0; ni < 8; ni++) {
            const int c = ni * 8 + lr4 * 2;
            *reinterpret_cast<float2*>(&Ps[(wq + lq) * PAD + c]) =
                make_float2(sfr[ni][0], sfr[ni][1]);
            *reinterpret_cast<float2*>(&Ps[(wq + lq + 8) * PAD + c]) =
                make_float2(sfr[ni][2], sfr[ni][3]);
        }
        __syncwarp();

        // ---- O += P · V ----
        uint32_t ap[8][4];
#pragma unroll
        for (int ki = 0; ki < 8; ki++) {
            const int c0 = ki * 8 + lr4;
            ap[ki][0] = fbits(Ps[(wq + lq) * PAD + c0]);
            ap[ki][1] = fbits(Ps[(wq + lq + 8) * PAD + c0]);
            ap[ki][2] = fbits(Ps[(wq + lq) * PAD + c0 + 4]);
            ap[ki][3] = fbits(Ps[(wq + lq + 8) * PAD + c0 + 4]);
        }
#pragma unroll
        for (int ni = 0; ni < 8; ni++) {
            const int d0 = ni * 8 + lq;
#pragma unroll
            for (int ki = 0; ki < 8; ki++) {
                const int kv0 = ki * 8 + lr4;
                uint32_t b0 = fbits(Vs[kv0 * PAD + d0]);
                uint32_t b1 = fbits(Vs[(kv0 + 4) * PAD + d0]);
                mma_tf32(oacc[ni], ap[ki][0], ap[ki][1], ap[ki][2], ap[ki][3], b0, b1);
            }
        }
        __syncwarp();   // P reads complete before next iteration overwrites
    }

    // ---- write output rows to g_attn [B,N,E] ----
    {
        const int b = bh / Hv, h = bh % Hv;
#pragma unroll
        for (int hh = 0; hh < 2; hh++) {
            const int row = wq + lq + hh * 8;
            const float inv = 1.f / lst[hh];
            const int n = qt * 128 + row;
            float* op = g_attn + ((size_t)b * Nv + n) * Ev + h * Dv;
#pragma unroll
            for (int ni = 0; ni < 8; ni++) {
                const int c = ni * 8 + lr4 * 2;
                *reinterpret_cast<float2*>(&op[c]) =
                    make_float2(oacc[ni][hh * 2 + 0] * inv,
                                oacc[ni][hh * 2 + 1] * inv);
            }
        }
    }
}

// ---------------------------------------------------------------------------
// kernel_launch
// ---------------------------------------------------------------------------
extern "C" void kernel_launch(void* const* d_in, const int* in_sizes, int n_in,
                              void* d_out, int out_size)
{
    const float* q  = (const float*)d_in[0];
    const float* k  = (const float*)d_in[1];
    const float* v  = (const float*)d_in[2];
    const float* Wq = (const float*)d_in[3];
    const float* bq = (const float*)d_in[4];
    const float* Wk = (const float*)d_in[5];
    const float* bk = (const float*)d_in[6];
    const float* Wv = (const float*)d_in[7];
    const float* bv = (const float*)d_in[8];
    const float* Wo = (const float*)d_in[9];
    const float* bo = (const float*)d_in[10];
    float* out = (float*)d_out;

    float *qp, *kp, *vp, *attn;
    cudaGetSymbolAddress((void**)&qp,   g_qp);
    cudaGetSymbolAddress((void**)&kp,   g_kp);
    cudaGetSymbolAddress((void**)&vp,   g_vp);
    cudaGetSymbolAddress((void**)&attn, g_attn);

    cudaFuncSetAttribute(flash_attn_mma,
                         cudaFuncAttributeMaxDynamicSharedMemorySize, FLASH_SMEM);
    cudaFuncSetAttribute(gemm_mma_qkv,
                         cudaFuncAttributeMaxDynamicSharedMemorySize, GEMM_SMEM);
    cudaFuncSetAttribute(gemm_mma_o,
                         cudaFuncAttributeMaxDynamicSharedMemorySize, GEMM_SMEM);

    const dim3 qkvgrid(Ev / 64, (Bv * Nv) / 128, 3);   // (8, 64, 3)
    gemm_mma_qkv<<<qkvgrid, 256, GEMM_SMEM>>>(q, k, v, Wq, Wk, Wv, bq, bk, bv,
                                              qp, kp, vp);

    flash_attn_mma<<<dim3(Nv / 128, Bv * Hv), 256, FLASH_SMEM>>>();

    const dim3 ogrid(Ev / 64, (Bv * Nv) / 128);        // (8, 64)
    gemm_mma_o<<<ogrid, 256, GEMM_SMEM>>>(attn, Wo, bo, out);
}